// round 1
// baseline (speedup 1.0000x reference)
#include <cuda_runtime.h>
#include <math.h>

#define Nn 131072
#define Dd 512
#define Kk 1024
#define ALPHA 32.0f
#define EPS 1e-5f

#define BM 128
#define BN 128
#define BK 16

// Scratch (allowed: __device__ globals, no runtime allocation)
__device__ float g_xn[(size_t)Nn * Dd];   // 256 MB normalized x
__device__ float g_x2[Nn];                // ||xn||^2 per row
__device__ float g_c2[Kk];                // ||c||^2 per center

// ---------------------------------------------------------------------------
// block reduction (full warps only). op: 0 = sum, 1 = min
// ---------------------------------------------------------------------------
__device__ __forceinline__ float block_reduce(float v, float* sm, int op) {
    int lane = threadIdx.x & 31, wid = threadIdx.x >> 5;
    #pragma unroll
    for (int o = 16; o; o >>= 1) {
        float t = __shfl_xor_sync(0xffffffffu, v, o);
        v = op ? fminf(v, t) : (v + t);
    }
    if (lane == 0) sm[wid] = v;
    __syncthreads();
    int nw = blockDim.x >> 5;
    if (wid == 0) {
        float r = (lane < nw) ? sm[lane] : (op ? 3.4e38f : 0.0f);
        #pragma unroll
        for (int o = 16; o; o >>= 1) {
            float t = __shfl_xor_sync(0xffffffffu, r, o);
            r = op ? fminf(r, t) : (r + t);
        }
        if (lane == 0) sm[0] = r;
    }
    __syncthreads();
    float r = sm[0];
    __syncthreads();   // allow smem reuse by a following reduction
    return r;
}

// ---------------------------------------------------------------------------
// Kernel 1: LayerNorm (torch variant: /(std+eps), biased std) + ||xn||^2
// grid = N blocks, 128 threads (each thread one float4 of the 512-row)
// ---------------------------------------------------------------------------
__global__ void ln_kernel(const float* __restrict__ x,
                          const float* __restrict__ w,
                          const float* __restrict__ b) {
    __shared__ float sm[32];
    size_t row = blockIdx.x;
    int t = threadIdx.x;
    float4 v = ((const float4*)(x + row * Dd))[t];

    float s = v.x + v.y + v.z + v.w;
    s = block_reduce(s, sm, 0);
    float mean = s * (1.0f / Dd);

    float d0 = v.x - mean, d1 = v.y - mean, d2 = v.z - mean, d3 = v.w - mean;
    float sq = d0 * d0 + d1 * d1 + d2 * d2 + d3 * d3;
    sq = block_reduce(sq, sm, 0);
    float stdv = sqrtf(sq * (1.0f / Dd));
    float inv = 1.0f / (stdv + EPS);

    float4 wv = ((const float4*)w)[t];
    float4 bv = ((const float4*)b)[t];
    float4 o;
    o.x = d0 * inv * wv.x + bv.x;
    o.y = d1 * inv * wv.y + bv.y;
    o.z = d2 * inv * wv.z + bv.z;
    o.w = d3 * inv * wv.w + bv.w;

    float n2 = o.x * o.x + o.y * o.y + o.z * o.z + o.w * o.w;
    n2 = block_reduce(n2, sm, 0);
    if (t == 0) g_x2[row] = n2;

    ((float4*)(g_xn + row * Dd))[t] = o;
}

// ---------------------------------------------------------------------------
// Kernel 2: per-center squared norms. grid = K blocks, 128 threads
// ---------------------------------------------------------------------------
__global__ void c2_kernel(const float* __restrict__ C) {
    __shared__ float sm[32];
    size_t row = blockIdx.x;
    float4 v = ((const float4*)(C + row * Dd))[threadIdx.x];
    float s = v.x * v.x + v.y * v.y + v.z * v.z + v.w * v.w;
    s = block_reduce(s, sm, 0);
    if (threadIdx.x == 0) g_c2[row] = s;
}

// ---------------------------------------------------------------------------
// Kernel 3: dist = sqrt(max(x2 + c2 - 2 * xn.C^T, 0))   (NT SGEMM, 128x128x16)
// grid = (K/BN, N/BM), 256 threads, 8x8 per-thread microtile
// ---------------------------------------------------------------------------
__global__ void __launch_bounds__(256, 2)
dist_gemm(const float* __restrict__ Cc, float* __restrict__ dist) {
    __shared__ float As[BK][BM];
    __shared__ float Bs[BK][BN];
    const float* A = g_xn;
    int bm = blockIdx.y * BM;
    int bn = blockIdx.x * BN;
    int tid = threadIdx.x;
    int tx = tid & 15, ty = tid >> 4;
    int lrow = tid >> 1;
    int lcol = (tid & 1) * 8;

    float acc[8][8];
    #pragma unroll
    for (int i = 0; i < 8; i++)
        #pragma unroll
        for (int j = 0; j < 8; j++) acc[i][j] = 0.0f;

    const float* aptr = A  + (size_t)(bm + lrow) * Dd + lcol;
    const float* bptr = Cc + (size_t)(bn + lrow) * Dd + lcol;

    for (int k0 = 0; k0 < Dd; k0 += BK) {
        float4 a0 = *(const float4*)(aptr + k0);
        float4 a1 = *(const float4*)(aptr + k0 + 4);
        float4 b0 = *(const float4*)(bptr + k0);
        float4 b1 = *(const float4*)(bptr + k0 + 4);
        __syncthreads();
        As[lcol + 0][lrow] = a0.x; As[lcol + 1][lrow] = a0.y;
        As[lcol + 2][lrow] = a0.z; As[lcol + 3][lrow] = a0.w;
        As[lcol + 4][lrow] = a1.x; As[lcol + 5][lrow] = a1.y;
        As[lcol + 6][lrow] = a1.z; As[lcol + 7][lrow] = a1.w;
        Bs[lcol + 0][lrow] = b0.x; Bs[lcol + 1][lrow] = b0.y;
        Bs[lcol + 2][lrow] = b0.z; Bs[lcol + 3][lrow] = b0.w;
        Bs[lcol + 4][lrow] = b1.x; Bs[lcol + 5][lrow] = b1.y;
        Bs[lcol + 6][lrow] = b1.z; Bs[lcol + 7][lrow] = b1.w;
        __syncthreads();
        #pragma unroll
        for (int kk = 0; kk < BK; kk++) {
            float4 af0 = *(const float4*)&As[kk][ty * 4];
            float4 af1 = *(const float4*)&As[kk][64 + ty * 4];
            float4 bf0 = *(const float4*)&Bs[kk][tx * 4];
            float4 bf1 = *(const float4*)&Bs[kk][64 + tx * 4];
            float a[8] = {af0.x, af0.y, af0.z, af0.w, af1.x, af1.y, af1.z, af1.w};
            float bb[8] = {bf0.x, bf0.y, bf0.z, bf0.w, bf1.x, bf1.y, bf1.z, bf1.w};
            #pragma unroll
            for (int i = 0; i < 8; i++)
                #pragma unroll
                for (int j = 0; j < 8; j++)
                    acc[i][j] += a[i] * bb[j];
        }
    }

    #pragma unroll
    for (int i = 0; i < 8; i++) {
        int rr = bm + ty * 4 + (i & 3) + (i >> 2) * 64;
        float x2v = g_x2[rr];
        #pragma unroll
        for (int j = 0; j < 8; j++) {
            int cc = bn + tx * 4 + (j & 3) + (j >> 2) * 64;
            float d2 = x2v + g_c2[cc] - 2.0f * acc[i][j];
            dist[(size_t)rr * Kk + cc] = sqrtf(fmaxf(d2, 0.0f));
        }
    }
}

// ---------------------------------------------------------------------------
// Kernel 4: softmax(-alpha * d) per row. grid = N blocks, 256 threads
// (row of 1024 = 4 floats/thread; min + sum reductions in-block, no atomics)
// ---------------------------------------------------------------------------
__global__ void softmax_kernel(const float* __restrict__ dist,
                               float* __restrict__ soft) {
    __shared__ float sm[32];
    size_t row = blockIdx.x;
    float4 v = ((const float4*)(dist + row * Kk))[threadIdx.x];
    float m = fminf(fminf(v.x, v.y), fminf(v.z, v.w));
    m = block_reduce(m, sm, 1);
    float4 e;
    e.x = expf(-ALPHA * (v.x - m));
    e.y = expf(-ALPHA * (v.y - m));
    e.z = expf(-ALPHA * (v.z - m));
    e.w = expf(-ALPHA * (v.w - m));
    float s = e.x + e.y + e.z + e.w;
    s = block_reduce(s, sm, 0);
    float inv = 1.0f / s;
    e.x *= inv; e.y *= inv; e.z *= inv; e.w *= inv;
    ((float4*)(soft + row * Kk))[threadIdx.x] = e;
}

// ---------------------------------------------------------------------------
// Kernel 5: rec = soft @ C   (NN SGEMM, 128x128x16)
// grid = (D/BN, N/BM), 256 threads
// ---------------------------------------------------------------------------
__global__ void __launch_bounds__(256, 2)
rec_gemm(const float* __restrict__ soft, const float* __restrict__ Cc,
         float* __restrict__ out) {
    __shared__ float As[BK][BM];
    __shared__ float Bs[BK][BN];
    int bm = blockIdx.y * BM;
    int bn = blockIdx.x * BN;
    int tid = threadIdx.x;
    int tx = tid & 15, ty = tid >> 4;
    int lrow = tid >> 1;
    int lcol = (tid & 1) * 8;
    int krow = tid >> 4;
    int cseg = (tid & 15) * 8;

    float acc[8][8];
    #pragma unroll
    for (int i = 0; i < 8; i++)
        #pragma unroll
        for (int j = 0; j < 8; j++) acc[i][j] = 0.0f;

    const float* aptr = soft + (size_t)(bm + lrow) * Kk + lcol;

    for (int k0 = 0; k0 < Kk; k0 += BK) {
        float4 a0 = *(const float4*)(aptr + k0);
        float4 a1 = *(const float4*)(aptr + k0 + 4);
        const float* bp = Cc + (size_t)(k0 + krow) * Dd + bn + cseg;
        float4 b0 = *(const float4*)(bp);
        float4 b1 = *(const float4*)(bp + 4);
        __syncthreads();
        As[lcol + 0][lrow] = a0.x; As[lcol + 1][lrow] = a0.y;
        As[lcol + 2][lrow] = a0.z; As[lcol + 3][lrow] = a0.w;
        As[lcol + 4][lrow] = a1.x; As[lcol + 5][lrow] = a1.y;
        As[lcol + 6][lrow] = a1.z; As[lcol + 7][lrow] = a1.w;
        *(float4*)&Bs[krow][cseg]     = b0;
        *(float4*)&Bs[krow][cseg + 4] = b1;
        __syncthreads();
        #pragma unroll
        for (int kk = 0; kk < BK; kk++) {
            float4 af0 = *(const float4*)&As[kk][ty * 4];
            float4 af1 = *(const float4*)&As[kk][64 + ty * 4];
            float4 bf0 = *(const float4*)&Bs[kk][tx * 4];
            float4 bf1 = *(const float4*)&Bs[kk][64 + tx * 4];
            float a[8] = {af0.x, af0.y, af0.z, af0.w, af1.x, af1.y, af1.z, af1.w};
            float bb[8] = {bf0.x, bf0.y, bf0.z, bf0.w, bf1.x, bf1.y, bf1.z, bf1.w};
            #pragma unroll
            for (int i = 0; i < 8; i++)
                #pragma unroll
                for (int j = 0; j < 8; j++)
                    acc[i][j] += a[i] * bb[j];
        }
    }

    #pragma unroll
    for (int i = 0; i < 8; i++) {
        int rr = bm + ty * 4 + (i & 3) + (i >> 2) * 64;
        #pragma unroll
        for (int j = 0; j < 8; j++) {
            int cc = bn + tx * 4 + (j & 3) + (j >> 2) * 64;
            out[(size_t)rr * Dd + cc] = acc[i][j];
        }
    }
}

// ---------------------------------------------------------------------------
extern "C" void kernel_launch(void* const* d_in, const int* in_sizes, int n_in,
                              void* d_out, int out_size) {
    const float* x = (const float*)d_in[0];          // (N, D)
    const float* w = (const float*)d_in[1];          // (D,)
    const float* b = (const float*)d_in[2];          // (D,)
    const float* C = (const float*)d_in[3];          // (K, D)

    float* out  = (float*)d_out;
    float* dist = out;                               // (N, K)
    float* soft = out + (size_t)Nn * Kk;             // (N, K)
    float* rec  = out + 2 * (size_t)Nn * Kk;         // (N, D)

    ln_kernel<<<Nn, 128>>>(x, w, b);
    c2_kernel<<<Kk, 128>>>(C);
    dist_gemm<<<dim3(Kk / BN, Nn / BM), 256>>>(C, dist);
    softmax_kernel<<<Nn, 256>>>(dist, soft);
    rec_gemm<<<dim3(Dd / BN, Nn / BM), 256>>>(soft, C, rec);
}

// round 8
// speedup vs baseline: 1.8504x; 1.8504x over previous
#include <cuda_runtime.h>
#include <cuda_bf16.h>
#include <cstdint>
#include <math.h>

#define Nn 131072
#define Dd 512
#define Kk 1024
#define ALPHA 32.0f
#define EPS 1e-5f

// GEMM tiling
#define BM 128
#define BN 128
#define KC 32                 // K elems per chunk
#define LDSB 80               // smem row stride bytes (64 data + 16 pad) — conflict-free
#define PLANE (128 * LDSB)    // one 128x32 bf16 plane
#define SSTAGE (4 * PLANE)    // Ahi, Alo, Bhi, Blo
#define EPI_LD 132            // epilogue f32 row stride (528B, 16B-aligned)
#define DSMEM (2 * SSTAGE)    // 81920 B

// Scratch (only ever referenced from DEVICE code — never as host-side kernel args)
__device__ float g_xn[(size_t)Nn * Dd];
__device__ float g_x2[Nn];
__device__ float g_c2[Kk];
__device__ float g_ct[(size_t)Dd * Kk];   // C^T (D x K)

// ───────── helpers ─────────
__device__ __forceinline__ void mma16816(float* c, uint32_t a0, uint32_t a1, uint32_t a2,
                                         uint32_t a3, uint32_t b0, uint32_t b1) {
    asm volatile("mma.sync.aligned.m16n8k16.row.col.f32.bf16.bf16.f32 "
                 "{%0,%1,%2,%3}, {%4,%5,%6,%7}, {%8,%9}, {%0,%1,%2,%3};"
                 : "+f"(c[0]), "+f"(c[1]), "+f"(c[2]), "+f"(c[3])
                 : "r"(a0), "r"(a1), "r"(a2), "r"(a3), "r"(b0), "r"(b1));
}
// bf16 hi/lo split of 4 floats
__device__ __forceinline__ void split4(float4 v, uint2& h, uint2& l) {
    __nv_bfloat16 h0 = __float2bfloat16(v.x), h1 = __float2bfloat16(v.y);
    __nv_bfloat16 h2 = __float2bfloat16(v.z), h3 = __float2bfloat16(v.w);
    __nv_bfloat16 l0 = __float2bfloat16(v.x - __bfloat162float(h0));
    __nv_bfloat16 l1 = __float2bfloat16(v.y - __bfloat162float(h1));
    __nv_bfloat16 l2 = __float2bfloat16(v.z - __bfloat162float(h2));
    __nv_bfloat16 l3 = __float2bfloat16(v.w - __bfloat162float(h3));
    __nv_bfloat162 a = __halves2bfloat162(h0, h1), b = __halves2bfloat162(h2, h3);
    __nv_bfloat162 c = __halves2bfloat162(l0, l1), d = __halves2bfloat162(l2, l3);
    h.x = *(uint32_t*)&a; h.y = *(uint32_t*)&b;
    l.x = *(uint32_t*)&c; l.y = *(uint32_t*)&d;
}

__device__ __forceinline__ float block_reduce(float v, float* sm, int op) {
    int lane = threadIdx.x & 31, wid = threadIdx.x >> 5;
    #pragma unroll
    for (int o = 16; o; o >>= 1) {
        float t = __shfl_xor_sync(0xffffffffu, v, o);
        v = op ? fminf(v, t) : (v + t);
    }
    if (lane == 0) sm[wid] = v;
    __syncthreads();
    int nw = blockDim.x >> 5;
    if (wid == 0) {
        float r = (lane < nw) ? sm[lane] : (op ? 3.4e38f : 0.0f);
        #pragma unroll
        for (int o = 16; o; o >>= 1) {
            float t = __shfl_xor_sync(0xffffffffu, r, o);
            r = op ? fminf(r, t) : (r + t);
        }
        if (lane == 0) sm[0] = r;
    }
    __syncthreads();
    float r = sm[0];
    __syncthreads();
    return r;
}

// ───────── layernorm ─────────
__global__ void ln_kernel(const float* __restrict__ x, const float* __restrict__ w,
                          const float* __restrict__ b) {
    __shared__ float sm[32];
    size_t row = blockIdx.x;
    int t = threadIdx.x;
    float4 v = ((const float4*)(x + row * Dd))[t];
    float s = block_reduce(v.x + v.y + v.z + v.w, sm, 0);
    float mean = s * (1.0f / Dd);
    float d0 = v.x - mean, d1 = v.y - mean, d2 = v.z - mean, d3 = v.w - mean;
    float sq = block_reduce(d0 * d0 + d1 * d1 + d2 * d2 + d3 * d3, sm, 0);
    float inv = 1.0f / (sqrtf(sq * (1.0f / Dd)) + EPS);
    float4 wv = ((const float4*)w)[t];
    float4 bv = ((const float4*)b)[t];
    float4 o;
    o.x = d0 * inv * wv.x + bv.x;  o.y = d1 * inv * wv.y + bv.y;
    o.z = d2 * inv * wv.z + bv.z;  o.w = d3 * inv * wv.w + bv.w;
    float n2 = block_reduce(o.x * o.x + o.y * o.y + o.z * o.z + o.w * o.w, sm, 0);
    if (t == 0) g_x2[row] = n2;
    ((float4*)(g_xn + row * Dd))[t] = o;
}

// ───────── center norms ─────────
__global__ void c2_kernel(const float* __restrict__ C) {
    __shared__ float sm[32];
    size_t row = blockIdx.x;
    float4 v = ((const float4*)(C + row * Dd))[threadIdx.x];
    float s = block_reduce(v.x * v.x + v.y * v.y + v.z * v.z + v.w * v.w, sm, 0);
    if (threadIdx.x == 0) g_c2[row] = s;
}

// ───────── transpose C → g_ct (D x K) ─────────
__global__ void transpose_c(const float* __restrict__ C) {
    __shared__ float t[32][33];
    int x = blockIdx.x * 32 + threadIdx.x;   // d
    int y = blockIdx.y * 32 + threadIdx.y;   // k
    #pragma unroll
    for (int j = 0; j < 4; j++)
        t[threadIdx.y + j * 8][threadIdx.x] = C[(size_t)(y + j * 8) * Dd + x];
    __syncthreads();
    int x2 = blockIdx.y * 32 + threadIdx.x;  // k
    int y2 = blockIdx.x * 32 + threadIdx.y;  // d
    #pragma unroll
    for (int j = 0; j < 4; j++)
        g_ct[(size_t)(y2 + j * 8) * Kk + x2] = t[threadIdx.x][threadIdx.y + j * 8];
}

// ───────── HMMA bf16x3 GEMM (both operands K-major) ─────────
// MODE 0 (dist): A = g_xn (device symbol), B = p0 (C), KTOT=512,
//                out = sqrt(max(x2 + c2 - 2*acc, 0)), ldo = Kk
// MODE 1 (rec):  A = p0 (soft), B = g_ct (device symbol), KTOT=1024, out = acc, ldo = Dd
template <int MODE>
__global__ void __launch_bounds__(256, 1)
mma_gemm(const float* __restrict__ p0, float* __restrict__ out) {
    constexpr int KTOT = (MODE == 0) ? Dd : Kk;
    constexpr int LDA  = (MODE == 0) ? Dd : Kk;
    constexpr int LDB  = (MODE == 0) ? Dd : Kk;
    constexpr int LDO  = (MODE == 0) ? Kk : Dd;
    const float* A = (MODE == 0) ? (const float*)g_xn : p0;
    const float* B = (MODE == 0) ? p0 : (const float*)g_ct;

    extern __shared__ char smc[];
    const int tid = threadIdx.x;
    const int wid = tid >> 5, lane = tid & 31;
    const int g = lane >> 2, tig = lane & 3;     // mma fragment coords
    const int wm = wid & 1, wn = wid >> 1;       // warp tile: 64 x 32
    const int bm = blockIdx.y * BM;
    const int bn = blockIdx.x * BN;
    constexpr int NC = KTOT / KC;

    float acc[4][4][4];
    #pragma unroll
    for (int i = 0; i < 4; i++)
        #pragma unroll
        for (int j = 0; j < 4; j++)
            #pragma unroll
            for (int q = 0; q < 4; q++) acc[i][j][q] = 0.0f;

    // loader lane mapping: 4 A + 4 B float4-loads per thread
    auto ldg = [&](int c, float4* av, float4* bv) {
        #pragma unroll
        for (int i = 0; i < 4; i++) {
            int li = tid + i * 256;
            int row = li >> 3, seg = li & 7;
            av[i] = *(const float4*)(A + (size_t)(bm + row) * LDA + c * KC + seg * 4);
            bv[i] = *(const float4*)(B + (size_t)(bn + row) * LDB + c * KC + seg * 4);
        }
    };
    auto sts = [&](int s, const float4* av, const float4* bv) {
        char* st = smc + s * SSTAGE;
        #pragma unroll
        for (int i = 0; i < 4; i++) {
            int li = tid + i * 256;
            int row = li >> 3, seg = li & 7;
            uint2 h, l;
            split4(av[i], h, l);
            *(uint2*)(st + 0 * PLANE + row * LDSB + seg * 8) = h;
            *(uint2*)(st + 1 * PLANE + row * LDSB + seg * 8) = l;
            split4(bv[i], h, l);
            *(uint2*)(st + 2 * PLANE + row * LDSB + seg * 8) = h;
            *(uint2*)(st + 3 * PLANE + row * LDSB + seg * 8) = l;
        }
    };

    {
        float4 av[4], bv[4];
        ldg(0, av, bv);
        sts(0, av, bv);
    }
    __syncthreads();

    for (int c = 0; c < NC; c++) {
        const int s = c & 1;
        float4 av[4], bv[4];
        if (c + 1 < NC) ldg(c + 1, av, bv);

        const char* stp = smc + s * SSTAGE;
        #pragma unroll
        for (int ks = 0; ks < 2; ks++) {
            // direct LDS fragment loads per PTX mma fragment spec
            uint32_t ah[4][4], al[4][4], bh[4][2], bl[4][2];
            #pragma unroll
            for (int fm = 0; fm < 4; fm++) {
                const char* ar = stp + (wm * 64 + fm * 16 + g) * LDSB + ks * 32 + tig * 4;
                ah[fm][0] = *(const uint32_t*)(ar);
                ah[fm][1] = *(const uint32_t*)(ar + 8 * LDSB);
                ah[fm][2] = *(const uint32_t*)(ar + 16);
                ah[fm][3] = *(const uint32_t*)(ar + 8 * LDSB + 16);
                al[fm][0] = *(const uint32_t*)(ar + PLANE);
                al[fm][1] = *(const uint32_t*)(ar + PLANE + 8 * LDSB);
                al[fm][2] = *(const uint32_t*)(ar + PLANE + 16);
                al[fm][3] = *(const uint32_t*)(ar + PLANE + 8 * LDSB + 16);
            }
            #pragma unroll
            for (int fn = 0; fn < 4; fn++) {
                const char* br = stp + 2 * PLANE + (wn * 32 + fn * 8 + g) * LDSB + ks * 32 + tig * 4;
                bh[fn][0] = *(const uint32_t*)(br);
                bh[fn][1] = *(const uint32_t*)(br + 16);
                bl[fn][0] = *(const uint32_t*)(br + PLANE);
                bl[fn][1] = *(const uint32_t*)(br + PLANE + 16);
            }
            #pragma unroll
            for (int fm = 0; fm < 4; fm++)
                #pragma unroll
                for (int fn = 0; fn < 4; fn++) {
                    mma16816(acc[fm][fn], ah[fm][0], ah[fm][1], ah[fm][2], ah[fm][3],
                             bh[fn][0], bh[fn][1]);
                    mma16816(acc[fm][fn], ah[fm][0], ah[fm][1], ah[fm][2], ah[fm][3],
                             bl[fn][0], bl[fn][1]);
                    mma16816(acc[fm][fn], al[fm][0], al[fm][1], al[fm][2], al[fm][3],
                             bh[fn][0], bh[fn][1]);
                }
        }
        if (c + 1 < NC) sts(1 - s, av, bv);
        __syncthreads();
    }

    // epilogue: stage into smem (stride EPI_LD f32), then coalesced out
    float* epi = (float*)smc;
    #pragma unroll
    for (int fm = 0; fm < 4; fm++) {
        int r0 = wm * 64 + fm * 16 + g;
        #pragma unroll
        for (int fn = 0; fn < 4; fn++) {
            int cc = wn * 32 + fn * 8 + 2 * tig;
            *(float2*)&epi[r0 * EPI_LD + cc]       = make_float2(acc[fm][fn][0], acc[fm][fn][1]);
            *(float2*)&epi[(r0 + 8) * EPI_LD + cc] = make_float2(acc[fm][fn][2], acc[fm][fn][3]);
        }
    }
    __syncthreads();
    #pragma unroll
    for (int i = 0; i < 16; i++) {
        int idx = tid + i * 256;
        int row = idx >> 5, c4 = (idx & 31) * 4;
        float4 v = *(float4*)&epi[row * EPI_LD + c4];
        if (MODE == 0) {
            float x2v = g_x2[bm + row];
            v.x = sqrtf(fmaxf(x2v + g_c2[bn + c4 + 0] - 2.0f * v.x, 0.0f));
            v.y = sqrtf(fmaxf(x2v + g_c2[bn + c4 + 1] - 2.0f * v.y, 0.0f));
            v.z = sqrtf(fmaxf(x2v + g_c2[bn + c4 + 2] - 2.0f * v.z, 0.0f));
            v.w = sqrtf(fmaxf(x2v + g_c2[bn + c4 + 3] - 2.0f * v.w, 0.0f));
        }
        *(float4*)(out + (size_t)(bm + row) * LDO + bn + c4) = v;
    }
}

// ───────── softmax(-alpha*d) ─────────
__global__ void softmax_kernel(const float* __restrict__ dist, float* __restrict__ soft) {
    __shared__ float sm[32];
    size_t row = blockIdx.x;
    float4 v = ((const float4*)(dist + row * Kk))[threadIdx.x];
    float m = block_reduce(fminf(fminf(v.x, v.y), fminf(v.z, v.w)), sm, 1);
    float4 e;
    e.x = expf(-ALPHA * (v.x - m));
    e.y = expf(-ALPHA * (v.y - m));
    e.z = expf(-ALPHA * (v.z - m));
    e.w = expf(-ALPHA * (v.w - m));
    float s = block_reduce(e.x + e.y + e.z + e.w, sm, 0);
    float inv = 1.0f / s;
    e.x *= inv; e.y *= inv; e.z *= inv; e.w *= inv;
    ((float4*)(soft + row * Kk))[threadIdx.x] = e;
}

// ───────── launch ─────────
extern "C" void kernel_launch(void* const* d_in, const int* in_sizes, int n_in,
                              void* d_out, int out_size) {
    const float* x = (const float*)d_in[0];
    const float* w = (const float*)d_in[1];
    const float* b = (const float*)d_in[2];
    const float* C = (const float*)d_in[3];

    float* out  = (float*)d_out;
    float* dist = out;
    float* soft = out + (size_t)Nn * Kk;
    float* rec  = out + 2 * (size_t)Nn * Kk;

    cudaFuncSetAttribute(mma_gemm<0>, cudaFuncAttributeMaxDynamicSharedMemorySize, DSMEM);
    cudaFuncSetAttribute(mma_gemm<1>, cudaFuncAttributeMaxDynamicSharedMemorySize, DSMEM);

    ln_kernel<<<Nn, 128>>>(x, w, b);
    c2_kernel<<<Kk, 128>>>(C);
    transpose_c<<<dim3(Dd / 32, Kk / 32), dim3(32, 8)>>>(C);

    // dist = sqrt(x2 + c2 - 2 * (g_xn @ C^T))
    mma_gemm<0><<<dim3(Kk / BN, Nn / BM), 256, DSMEM>>>(C, dist);
    softmax_kernel<<<Nn, 256>>>(dist, soft);
    // rec = soft @ C  (B = g_ct)
    mma_gemm<1><<<dim3(Dd / BN, Nn / BM), 256, DSMEM>>>(soft, rec);
}